// round 4
// baseline (speedup 1.0000x reference)
#include <cuda_runtime.h>
#include <cuda_bf16.h>
#include <cstdint>

#define BGR   128          // graphs
#define EPG   4096         // edges per graph
#define ETOT  (BGR*EPG)    // 524288 edges
#define FDIM  128
#define NTMAX (BGR*512)    // 65536 max nodes

// ---------------- device scratch ----------------
__device__ float g_bufA[NTMAX*FDIM];   // Xa (aggregated input)
__device__ float g_bufB[NTMAX*FDIM];   // H  (post-GEMM features)
__device__ float g_bufC[NTMAX*FDIM];   // xnew (next-stage input)
__device__ float g_s0   [NTMAX];
__device__ int   g_src[ETOT];
__device__ int   g_dst[ETOT];
__device__ int   g_csr_src[ETOT];
__device__ float g_csr_w [ETOT];
__device__ int   g_cnt   [NTMAX];
__device__ int   g_off   [NTMAX];
__device__ int   g_topi  [BGR*256];
__device__ float g_topt  [BGR*256];    // tanh(topv)
__device__ int   g_newidx[NTMAX];

// =====================================================================
// Fused per-graph prep: remap + mask + count + dinv + scan + CSR fill
// =====================================================================
template<int NPG, int REMAP, int WRITEBACK>
__global__ __launch_bounds__(512)
void k_prep(const int* __restrict__ esrc, const int* __restrict__ edst,
            const int* __restrict__ newidx,
            int* __restrict__ osrc, int* __restrict__ odst,
            int* __restrict__ cnt, int* __restrict__ off,
            int* __restrict__ csr_src, float* __restrict__ csr_w) {
    __shared__ int   s_cnt [NPG];
    __shared__ int   s_cur [NPG];
    __shared__ float s_dinv[NPG];
    const int b = blockIdx.x, t = threadIdx.x;
    const int ebase = b * EPG;
    const int nbase = b * NPG;
    if (t < NPG) s_cnt[t] = 0;
    __syncthreads();

    int ls[8], ldst[8];
#pragma unroll
    for (int u = 0; u < 8; u++) {
        int e = ebase + u*512 + t;
        int s = esrc[e], d = edst[e];
        if (REMAP) {
            if (d >= 0) {
                int ns = newidx[s], nd = newidx[d];
                if (ns < 0 || nd < 0) d = -1;
                else { s = ns; d = nd; }
            }
        }
        if (WRITEBACK) { osrc[e] = s; odst[e] = d; }
        if (d >= 0) {
            ls[u]   = s - nbase;
            ldst[u] = d - nbase;
            atomicAdd(&s_cnt[ldst[u]], 1);
        } else ldst[u] = -1;
    }
    __syncthreads();

    int c = (t < NPG) ? s_cnt[t] : 0;
    if (t < NPG) {
        cnt[nbase + t] = c;
        s_dinv[t] = rsqrtf((float)c + 1.f);
        s_cur[t]  = c;
    }
    __syncthreads();
    for (int sft = 1; sft < NPG; sft <<= 1) {
        int add = (t >= sft && t < NPG) ? s_cur[t - sft] : 0;
        __syncthreads();
        if (t < NPG) s_cur[t] += add;
        __syncthreads();
    }
    if (t < NPG) {
        int o = s_cur[t] - c;
        off[nbase + t] = ebase + o;
        s_cur[t] = o;
    }
    __syncthreads();

#pragma unroll
    for (int u = 0; u < 8; u++) {
        if (ldst[u] >= 0) {
            int pos = ebase + atomicAdd(&s_cur[ldst[u]], 1);
            csr_src[pos] = nbase + ls[u];
            csr_w [pos]  = s_dinv[ls[u]] * s_dinv[ldst[u]];
        }
    }
}

// =====================================================================
// Aggregation: Xa[i] = X[i]/(deg+1) + sum_j w_ij X[j]  (warp/node, MLP=4)
// =====================================================================
__global__ __launch_bounds__(256)
void k_agg(const float* __restrict__ X, const int* __restrict__ cnt,
           const int* __restrict__ off, const int* __restrict__ csr_src,
           const float* __restrict__ csr_w, float* __restrict__ Xa, int nt) {
    int warp = (blockIdx.x*256 + threadIdx.x) >> 5;
    int lane = threadIdx.x & 31;
    if (warp >= nt) return;
    int i = warp;
    int c = cnt[i], o = off[i];
    float self = 1.f / ((float)c + 1.f);
    float4 hv = *(const float4*)(X + (size_t)i*128 + lane*4);
    float4 a0 = make_float4(self*hv.x, self*hv.y, self*hv.z, self*hv.w);
    float4 a1 = make_float4(0,0,0,0), a2 = make_float4(0,0,0,0), a3 = make_float4(0,0,0,0);
    int j = 0;
    for (; j + 4 <= c; j += 4) {
        int   s0 = csr_src[o+j],   s1 = csr_src[o+j+1];
        int   s2 = csr_src[o+j+2], s3 = csr_src[o+j+3];
        float w0 = csr_w[o+j],   w1 = csr_w[o+j+1];
        float w2 = csr_w[o+j+2], w3 = csr_w[o+j+3];
        float4 h0 = *(const float4*)(X + (size_t)s0*128 + lane*4);
        float4 h1 = *(const float4*)(X + (size_t)s1*128 + lane*4);
        float4 h2 = *(const float4*)(X + (size_t)s2*128 + lane*4);
        float4 h3 = *(const float4*)(X + (size_t)s3*128 + lane*4);
        a0.x += w0*h0.x; a0.y += w0*h0.y; a0.z += w0*h0.z; a0.w += w0*h0.w;
        a1.x += w1*h1.x; a1.y += w1*h1.y; a1.z += w1*h1.z; a1.w += w1*h1.w;
        a2.x += w2*h2.x; a2.y += w2*h2.y; a2.z += w2*h2.z; a2.w += w2*h2.w;
        a3.x += w3*h3.x; a3.y += w3*h3.y; a3.z += w3*h3.z; a3.w += w3*h3.w;
    }
    for (; j < c; j++) {
        int s = csr_src[o+j]; float w = csr_w[o+j];
        float4 hs = *(const float4*)(X + (size_t)s*128 + lane*4);
        a0.x += w*hs.x; a0.y += w*hs.y; a0.z += w*hs.z; a0.w += w*hs.w;
    }
    a0.x += a1.x + a2.x + a3.x;
    a0.y += a1.y + a2.y + a3.y;
    a0.z += a1.z + a2.z + a3.z;
    a0.w += a1.w + a2.w + a3.w;
    *(float4*)(Xa + (size_t)i*128 + lane*4) = a0;
}

// =====================================================================
// Tensor-core GEMM (split-bf16, 3 MMA terms):
//   H[M,128] = relu(Xa @ W + b); epilogue also computes s0 = H.Ws
// Block: 128x128 tile, 256 thr = 8 warps (4M x 2N), warp tile 32x64.
// =====================================================================
__device__ __forceinline__ void mma_bf16(float* d, const unsigned* a, const unsigned* b) {
    asm volatile(
        "mma.sync.aligned.m16n8k16.row.col.f32.bf16.bf16.f32 "
        "{%0,%1,%2,%3}, {%4,%5,%6,%7}, {%8,%9}, {%0,%1,%2,%3};\n"
        : "+f"(d[0]), "+f"(d[1]), "+f"(d[2]), "+f"(d[3])
        : "r"(a[0]), "r"(a[1]), "r"(a[2]), "r"(a[3]), "r"(b[0]), "r"(b[1]));
}

__global__ __launch_bounds__(256)
void k_gemm_tc(const float* __restrict__ A, const float* __restrict__ W,
               const float* __restrict__ bias, const float* __restrict__ Ws,
               float* __restrict__ C, float* __restrict__ s0) {
    __shared__ __align__(16) __nv_bfloat16 As_hi[128][40];
    __shared__ __align__(16) __nv_bfloat16 As_lo[128][40];
    __shared__ __align__(16) __nv_bfloat16 Bt_hi[128][40];
    __shared__ __align__(16) __nv_bfloat16 Bt_lo[128][40];
    __shared__ float s0part[2][128];

    const int t = threadIdx.x;
    const int warp = t >> 5, lane = t & 31;
    const int warpM = warp >> 1, warpN = warp & 1;
    const int row0 = blockIdx.x * 128;
    const int lq = lane >> 2;       // 0..7
    const int lr = lane & 3;        // 0..3

    float acc[2][8][4];
#pragma unroll
    for (int mt = 0; mt < 2; mt++)
#pragma unroll
        for (int nt = 0; nt < 8; nt++)
#pragma unroll
            for (int r = 0; r < 4; r++) acc[mt][nt][r] = 0.f;

    for (int kc = 0; kc < 4; kc++) {
        // --- load A chunk [128 rows x 32 k] ---
#pragma unroll
        for (int it = 0; it < 4; it++) {
            int idx = t + it*256;            // 0..1023 float4 slots
            int row = idx >> 3;
            int kq  = (idx & 7) * 4;
            float4 v = *(const float4*)(A + (size_t)(row0 + row)*128 + kc*32 + kq);
            float f[4] = {v.x, v.y, v.z, v.w};
#pragma unroll
            for (int e = 0; e < 4; e++) {
                __nv_bfloat16 h = __float2bfloat16(f[e]);
                As_hi[row][kq + e] = h;
                As_lo[row][kq + e] = __float2bfloat16(f[e] - __bfloat162float(h));
            }
        }
        // --- load W chunk [32 k x 128 n] transposed -> Bt[n][k] ---
#pragma unroll
        for (int it = 0; it < 4; it++) {
            int idx = t + it*256;
            int kk = idx >> 5;               // 32 float4 per k-row
            int nq = (idx & 31) * 4;
            float4 v = *(const float4*)(W + (size_t)(kc*32 + kk)*128 + nq);
            float f[4] = {v.x, v.y, v.z, v.w};
#pragma unroll
            for (int e = 0; e < 4; e++) {
                __nv_bfloat16 h = __float2bfloat16(f[e]);
                Bt_hi[nq + e][kk] = h;
                Bt_lo[nq + e][kk] = __float2bfloat16(f[e] - __bfloat162float(h));
            }
        }
        __syncthreads();

#pragma unroll
        for (int ks = 0; ks < 2; ks++) {
            const int kb = ks * 16;
            unsigned a_hi[2][4], a_lo[2][4], b_hi[8][2], b_lo[8][2];
#pragma unroll
            for (int mt = 0; mt < 2; mt++) {
                int m = warpM*32 + mt*16 + lq;
                a_hi[mt][0] = *(const unsigned*)&As_hi[m    ][kb + 2*lr];
                a_hi[mt][1] = *(const unsigned*)&As_hi[m + 8][kb + 2*lr];
                a_hi[mt][2] = *(const unsigned*)&As_hi[m    ][kb + 2*lr + 8];
                a_hi[mt][3] = *(const unsigned*)&As_hi[m + 8][kb + 2*lr + 8];
                a_lo[mt][0] = *(const unsigned*)&As_lo[m    ][kb + 2*lr];
                a_lo[mt][1] = *(const unsigned*)&As_lo[m + 8][kb + 2*lr];
                a_lo[mt][2] = *(const unsigned*)&As_lo[m    ][kb + 2*lr + 8];
                a_lo[mt][3] = *(const unsigned*)&As_lo[m + 8][kb + 2*lr + 8];
            }
#pragma unroll
            for (int nt = 0; nt < 8; nt++) {
                int n = warpN*64 + nt*8 + lq;
                b_hi[nt][0] = *(const unsigned*)&Bt_hi[n][kb + 2*lr];
                b_hi[nt][1] = *(const unsigned*)&Bt_hi[n][kb + 2*lr + 8];
                b_lo[nt][0] = *(const unsigned*)&Bt_lo[n][kb + 2*lr];
                b_lo[nt][1] = *(const unsigned*)&Bt_lo[n][kb + 2*lr + 8];
            }
#pragma unroll
            for (int mt = 0; mt < 2; mt++)
#pragma unroll
                for (int nt = 0; nt < 8; nt++) {
                    mma_bf16(acc[mt][nt], a_hi[mt], b_hi[nt]);
                    mma_bf16(acc[mt][nt], a_lo[mt], b_hi[nt]);
                    mma_bf16(acc[mt][nt], a_hi[mt], b_lo[nt]);
                }
        }
        __syncthreads();
    }

    // --- epilogue: bias + relu + store + fused s0 = H.Ws ---
    float pacc[2][2] = {{0.f,0.f},{0.f,0.f}};
#pragma unroll
    for (int nt = 0; nt < 8; nt++) {
        int n0 = warpN*64 + nt*8 + 2*lr;
        float bb0 = __ldg(bias + n0), bb1 = __ldg(bias + n0 + 1);
        float ww0 = __ldg(Ws + n0),   ww1 = __ldg(Ws + n0 + 1);
#pragma unroll
        for (int mt = 0; mt < 2; mt++) {
            int r0 = warpM*32 + mt*16 + lq;
            float v0 = fmaxf(acc[mt][nt][0] + bb0, 0.f);
            float v1 = fmaxf(acc[mt][nt][1] + bb1, 0.f);
            float v2 = fmaxf(acc[mt][nt][2] + bb0, 0.f);
            float v3 = fmaxf(acc[mt][nt][3] + bb1, 0.f);
            *(float2*)(C + (size_t)(row0 + r0)*128 + n0)     = make_float2(v0, v1);
            *(float2*)(C + (size_t)(row0 + r0 + 8)*128 + n0) = make_float2(v2, v3);
            pacc[mt][0] += v0*ww0 + v1*ww1;
            pacc[mt][1] += v2*ww0 + v3*ww1;
        }
    }
#pragma unroll
    for (int mt = 0; mt < 2; mt++)
#pragma unroll
        for (int h = 0; h < 2; h++) {
            float p = pacc[mt][h];
            p += __shfl_xor_sync(0xFFFFFFFFu, p, 1);
            p += __shfl_xor_sync(0xFFFFFFFFu, p, 2);
            if (lr == 0) s0part[warpN][warpM*32 + mt*16 + lq + h*8] = p;
        }
    __syncthreads();
    if (t < 128) s0[row0 + t] = s0part[0][t] + s0part[1][t];
}

// =====================================================================
// Fused score-GCN + per-graph exact top-k (bitonic)
// =====================================================================
template<int NPG>
__global__ void k_topk(const int* __restrict__ cnt, const int* __restrict__ off,
                       const int* __restrict__ csr_src, const float* __restrict__ csr_w,
                       const float* __restrict__ s0, const float* __restrict__ bs,
                       int* __restrict__ topi, float* __restrict__ topt,
                       int* __restrict__ newidx) {
    constexpr int K = NPG/2;
    __shared__ unsigned long long keys[NPG];
    __shared__ float s_sc[NPG];
    int b = blockIdx.x, i = threadIdx.x;
    int gi = b*NPG + i;
    int c = cnt[gi], o = off[gi];
    float acc = bs[0] + s0[gi] / ((float)c + 1.f);
    for (int j = 0; j < c; j++) acc += csr_w[o+j] * s0[csr_src[o+j]];
    s_sc[i] = acc;
    unsigned u  = __float_as_uint(acc);
    unsigned ou = u ^ ((u & 0x80000000u) ? 0xFFFFFFFFu : 0x80000000u);
    keys[i] = ((unsigned long long)(~ou) << 32) | (unsigned)i;
    __syncthreads();
    for (int kk = 2; kk <= NPG; kk <<= 1) {
        for (int j = kk >> 1; j > 0; j >>= 1) {
            int ixj = i ^ j;
            if (ixj > i) {
                bool up = ((i & kk) == 0);
                unsigned long long a = keys[i], cc = keys[ixj];
                if ((a > cc) == up) { keys[i] = cc; keys[ixj] = a; }
            }
            __syncthreads();
        }
    }
    int idx = (int)(keys[i] & 0xFFFFFFFFull);
    if (i < K) {
        topi[b*K + i] = idx;
        topt[b*K + i] = tanhf(s_sc[idx]);
        newidx[b*NPG + idx] = b*K + i;
    } else {
        newidx[b*NPG + idx] = -1;
    }
}

// =====================================================================
// Fused gather*tanh + readout (max / mean), writes xnew for next stage
// =====================================================================
template<int NPG, int ACCUM>
__global__ __launch_bounds__(128)
void k_xr(const float* __restrict__ H, const int* __restrict__ topi,
          const float* __restrict__ topt, float* __restrict__ xnew,
          float* __restrict__ out) {
    constexpr int K = NPG/2;
    __shared__ int   s_old[K];
    __shared__ float s_t  [K];
    int b = blockIdx.x, cth = threadIdx.x;
    for (int j = cth; j < K; j += 128) { s_old[j] = topi[b*K + j]; s_t[j] = topt[b*K + j]; }
    __syncthreads();
    float mx = -3.402823466e38f, sm = 0.f;
#pragma unroll 4
    for (int j = 0; j < K; j++) {
        float v = H[(size_t)(b*NPG + s_old[j])*128 + cth] * s_t[j];
        xnew[(size_t)(b*K + j)*128 + cth] = v;
        mx = fmaxf(mx, v); sm += v;
    }
    if (ACCUM) {
        out[b*256 + cth]       += mx;
        out[b*256 + 128 + cth] += sm / (float)K;
    } else {
        out[b*256 + cth]       = mx;
        out[b*256 + 128 + cth] = sm / (float)K;
    }
}

// =====================================================================
extern "C" void kernel_launch(void* const* d_in, const int* in_sizes, int n_in,
                              void* d_out, int out_size) {
    const float* x   = (const float*)d_in[0];
    const int*   ei  = (const int*)  d_in[1];
    const float* W1  = (const float*)d_in[3];
    const float* b1  = (const float*)d_in[4];
    const float* Ws1 = (const float*)d_in[5];
    const float* bs1 = (const float*)d_in[6];
    const float* W2  = (const float*)d_in[7];
    const float* b2  = (const float*)d_in[8];
    const float* Ws2 = (const float*)d_in[9];
    const float* bs2 = (const float*)d_in[10];
    const float* W3  = (const float*)d_in[11];
    const float* b3  = (const float*)d_in[12];
    const float* Ws3 = (const float*)d_in[13];
    const float* bs3 = (const float*)d_in[14];
    float* out = (float*)d_out;

    float *bufA, *bufB, *bufC, *s0p, *csrw, *topt;
    int *srcp, *dstp, *csrs, *cntp, *offp, *topip, *newip;
    cudaGetSymbolAddress((void**)&bufA,  g_bufA);
    cudaGetSymbolAddress((void**)&bufB,  g_bufB);
    cudaGetSymbolAddress((void**)&bufC,  g_bufC);
    cudaGetSymbolAddress((void**)&s0p,   g_s0);
    cudaGetSymbolAddress((void**)&csrw,  g_csr_w);
    cudaGetSymbolAddress((void**)&topt,  g_topt);
    cudaGetSymbolAddress((void**)&srcp,  g_src);
    cudaGetSymbolAddress((void**)&dstp,  g_dst);
    cudaGetSymbolAddress((void**)&csrs,  g_csr_src);
    cudaGetSymbolAddress((void**)&cntp,  g_cnt);
    cudaGetSymbolAddress((void**)&offp,  g_off);
    cudaGetSymbolAddress((void**)&topip, g_topi);
    cudaGetSymbolAddress((void**)&newip, g_newidx);

    const int* ei_src = ei;
    const int* ei_dst = ei + ETOT;

    // ---------------- stage 1: n=512, k=256 ----------------
    {
        const int NT = BGR*512;
        k_prep<512,0,0><<<BGR,512>>>(ei_src, ei_dst, newip, srcp, dstp,
                                     cntp, offp, csrs, csrw);
        k_agg <<<NT/8,256>>>(x, cntp, offp, csrs, csrw, bufA, NT);
        k_gemm_tc<<<NT/128,256>>>(bufA, W1, b1, Ws1, bufB, s0p);
        k_topk<512><<<BGR,512>>>(cntp, offp, csrs, csrw, s0p, bs1, topip, topt, newip);
        k_xr<512,0><<<BGR,128>>>(bufB, topip, topt, bufC, out);
    }
    // ---------------- stage 2: n=256, k=128 ----------------
    {
        const int NT = BGR*256;
        k_prep<256,1,1><<<BGR,512>>>(ei_src, ei_dst, newip, srcp, dstp,
                                     cntp, offp, csrs, csrw);
        k_agg <<<NT/8,256>>>(bufC, cntp, offp, csrs, csrw, bufA, NT);
        k_gemm_tc<<<NT/128,256>>>(bufA, W2, b2, Ws2, bufB, s0p);
        k_topk<256><<<BGR,256>>>(cntp, offp, csrs, csrw, s0p, bs2, topip, topt, newip);
        k_xr<256,1><<<BGR,128>>>(bufB, topip, topt, bufC, out);
    }
    // ---------------- stage 3: n=128, k=64 ----------------
    {
        const int NT = BGR*128;
        k_prep<128,1,0><<<BGR,512>>>(srcp, dstp, newip, srcp, dstp,
                                     cntp, offp, csrs, csrw);
        k_agg <<<NT/8,256>>>(bufC, cntp, offp, csrs, csrw, bufA, NT);
        k_gemm_tc<<<NT/128,256>>>(bufA, W3, b3, Ws3, bufB, s0p);
        k_topk<128><<<BGR,128>>>(cntp, offp, csrs, csrw, s0p, bs3, topip, topt, newip);
        k_xr<128,1><<<BGR,128>>>(bufB, topip, topt, bufC, out);
    }
}

// round 5
// speedup vs baseline: 1.2481x; 1.2481x over previous
#include <cuda_runtime.h>
#include <cuda_bf16.h>
#include <cstdint>

#define BGR   128          // graphs
#define EPG   4096         // edges per graph
#define ETOT  (BGR*EPG)    // 524288 edges
#define FDIM  128
#define NTMAX (BGR*512)    // 65536 max nodes

// ---------------- device scratch ----------------
__device__ __nv_bfloat16 g_Xa_hi[NTMAX*FDIM];   // aggregated input, split bf16
__device__ __nv_bfloat16 g_Xa_lo[NTMAX*FDIM];
__device__ __nv_bfloat16 g_Wt_hi[FDIM*FDIM];    // W transposed [n][k], split bf16
__device__ __nv_bfloat16 g_Wt_lo[FDIM*FDIM];
__device__ float g_bufB[NTMAX*FDIM];   // H  (post-GEMM features)
__device__ float g_bufC[NTMAX*FDIM];   // xnew (next-stage input)
__device__ float g_s0   [NTMAX];
__device__ int   g_src[ETOT];
__device__ int   g_dst[ETOT];
__device__ int   g_csr_src[ETOT];
__device__ float g_csr_w [ETOT];
__device__ int   g_cnt   [NTMAX];
__device__ int   g_off   [NTMAX];
__device__ int   g_topi  [BGR*256];
__device__ float g_topt  [BGR*256];    // tanh(topv)
__device__ int   g_newidx[NTMAX];

// =====================================================================
// Fused per-graph prep: remap + mask + count + dinv + scan + CSR fill.
// Extra block (b == BGR) converts W -> transposed split-bf16 (runs
// concurrently with the 128 per-graph blocks; saves a separate launch).
// =====================================================================
template<int NPG, int REMAP, int WRITEBACK>
__global__ __launch_bounds__(512)
void k_prep(const int* __restrict__ esrc, const int* __restrict__ edst,
            const int* __restrict__ newidx,
            int* __restrict__ osrc, int* __restrict__ odst,
            int* __restrict__ cnt, int* __restrict__ off,
            int* __restrict__ csr_src, float* __restrict__ csr_w,
            const float* __restrict__ W,
            __nv_bfloat16* __restrict__ Wt_hi, __nv_bfloat16* __restrict__ Wt_lo) {
    const int b = blockIdx.x, t = threadIdx.x;
    if (b == BGR) {
        // transpose + split W[128k][128n] -> Wt[n][k]
#pragma unroll
        for (int it = 0; it < 32; it++) {
            int idx = t + it*512;          // 0..16383
            int n = idx >> 7, k = idx & 127;
            float v = W[k*128 + n];
            __nv_bfloat16 h = __float2bfloat16(v);
            Wt_hi[idx] = h;
            Wt_lo[idx] = __float2bfloat16(v - __bfloat162float(h));
        }
        return;
    }
    __shared__ int   s_cnt [NPG];
    __shared__ int   s_cur [NPG];
    __shared__ float s_dinv[NPG];
    const int ebase = b * EPG;
    const int nbase = b * NPG;
    if (t < NPG) s_cnt[t] = 0;
    __syncthreads();

    int ls[8], ldst[8];
#pragma unroll
    for (int u = 0; u < 8; u++) {
        int e = ebase + u*512 + t;
        int s = esrc[e], d = edst[e];
        if (REMAP) {
            if (d >= 0) {
                int ns = newidx[s], nd = newidx[d];
                if (ns < 0 || nd < 0) d = -1;
                else { s = ns; d = nd; }
            }
        }
        if (WRITEBACK) { osrc[e] = s; odst[e] = d; }
        if (d >= 0) {
            ls[u]   = s - nbase;
            ldst[u] = d - nbase;
            atomicAdd(&s_cnt[ldst[u]], 1);
        } else ldst[u] = -1;
    }
    __syncthreads();

    int c = (t < NPG) ? s_cnt[t] : 0;
    if (t < NPG) {
        cnt[nbase + t] = c;
        s_dinv[t] = rsqrtf((float)c + 1.f);
        s_cur[t]  = c;
    }
    __syncthreads();
    for (int sft = 1; sft < NPG; sft <<= 1) {
        int add = (t >= sft && t < NPG) ? s_cur[t - sft] : 0;
        __syncthreads();
        if (t < NPG) s_cur[t] += add;
        __syncthreads();
    }
    if (t < NPG) {
        int o = s_cur[t] - c;
        off[nbase + t] = ebase + o;
        s_cur[t] = o;
    }
    __syncthreads();

#pragma unroll
    for (int u = 0; u < 8; u++) {
        if (ldst[u] >= 0) {
            int pos = ebase + atomicAdd(&s_cur[ldst[u]], 1);
            csr_src[pos] = nbase + ls[u];
            csr_w [pos]  = s_dinv[ls[u]] * s_dinv[ldst[u]];
        }
    }
}

// =====================================================================
// Aggregation: Xa[i] = X[i]/(deg+1) + sum_j w_ij X[j]  (warp/node, MLP=4)
// Output written directly as split bf16 for the tensor-core GEMM.
// =====================================================================
__global__ __launch_bounds__(256)
void k_agg(const float* __restrict__ X, const int* __restrict__ cnt,
           const int* __restrict__ off, const int* __restrict__ csr_src,
           const float* __restrict__ csr_w,
           __nv_bfloat16* __restrict__ Xa_hi, __nv_bfloat16* __restrict__ Xa_lo,
           int nt) {
    int warp = (blockIdx.x*256 + threadIdx.x) >> 5;
    int lane = threadIdx.x & 31;
    if (warp >= nt) return;
    int i = warp;
    int c = cnt[i], o = off[i];
    float self = 1.f / ((float)c + 1.f);
    float4 hv = *(const float4*)(X + (size_t)i*128 + lane*4);
    float4 a0 = make_float4(self*hv.x, self*hv.y, self*hv.z, self*hv.w);
    float4 a1 = make_float4(0,0,0,0), a2 = make_float4(0,0,0,0), a3 = make_float4(0,0,0,0);
    int j = 0;
    for (; j + 4 <= c; j += 4) {
        int   s0 = csr_src[o+j],   s1 = csr_src[o+j+1];
        int   s2 = csr_src[o+j+2], s3 = csr_src[o+j+3];
        float w0 = csr_w[o+j],   w1 = csr_w[o+j+1];
        float w2 = csr_w[o+j+2], w3 = csr_w[o+j+3];
        float4 h0 = *(const float4*)(X + (size_t)s0*128 + lane*4);
        float4 h1 = *(const float4*)(X + (size_t)s1*128 + lane*4);
        float4 h2 = *(const float4*)(X + (size_t)s2*128 + lane*4);
        float4 h3 = *(const float4*)(X + (size_t)s3*128 + lane*4);
        a0.x += w0*h0.x; a0.y += w0*h0.y; a0.z += w0*h0.z; a0.w += w0*h0.w;
        a1.x += w1*h1.x; a1.y += w1*h1.y; a1.z += w1*h1.z; a1.w += w1*h1.w;
        a2.x += w2*h2.x; a2.y += w2*h2.y; a2.z += w2*h2.z; a2.w += w2*h2.w;
        a3.x += w3*h3.x; a3.y += w3*h3.y; a3.z += w3*h3.z; a3.w += w3*h3.w;
    }
    for (; j < c; j++) {
        int s = csr_src[o+j]; float w = csr_w[o+j];
        float4 hs = *(const float4*)(X + (size_t)s*128 + lane*4);
        a0.x += w*hs.x; a0.y += w*hs.y; a0.z += w*hs.z; a0.w += w*hs.w;
    }
    a0.x += a1.x + a2.x + a3.x;
    a0.y += a1.y + a2.y + a3.y;
    a0.z += a1.z + a2.z + a3.z;
    a0.w += a1.w + a2.w + a3.w;
    // split-bf16 store: 4 hi + 4 lo as one 8-byte store each
    float f[4] = {a0.x, a0.y, a0.z, a0.w};
    __nv_bfloat16 hi4[4], lo4[4];
#pragma unroll
    for (int e = 0; e < 4; e++) {
        hi4[e] = __float2bfloat16(f[e]);
        lo4[e] = __float2bfloat16(f[e] - __bfloat162float(hi4[e]));
    }
    *(uint2*)(Xa_hi + (size_t)i*128 + lane*4) = *(uint2*)hi4;
    *(uint2*)(Xa_lo + (size_t)i*128 + lane*4) = *(uint2*)lo4;
}

// =====================================================================
// Tensor-core GEMM (split-bf16 operands preconverted; 3 MMA terms):
//   H[M,128] = relu(Xa @ W + b); epilogue also computes s0 = H.Ws
// Block: 128x128 tile, 256 thr = 8 warps (4M x 2N), warp tile 32x64.
// =====================================================================
__device__ __forceinline__ void mma_bf16(float* d, const unsigned* a, const unsigned* b) {
    asm volatile(
        "mma.sync.aligned.m16n8k16.row.col.f32.bf16.bf16.f32 "
        "{%0,%1,%2,%3}, {%4,%5,%6,%7}, {%8,%9}, {%0,%1,%2,%3};\n"
        : "+f"(d[0]), "+f"(d[1]), "+f"(d[2]), "+f"(d[3])
        : "r"(a[0]), "r"(a[1]), "r"(a[2]), "r"(a[3]), "r"(b[0]), "r"(b[1]));
}

__global__ __launch_bounds__(256)
void k_gemm_tc(const __nv_bfloat16* __restrict__ A_hi,
               const __nv_bfloat16* __restrict__ A_lo,
               const __nv_bfloat16* __restrict__ Wt_hi,
               const __nv_bfloat16* __restrict__ Wt_lo,
               const float* __restrict__ bias, const float* __restrict__ Ws,
               float* __restrict__ C, float* __restrict__ s0) {
    __shared__ __align__(16) __nv_bfloat16 As_hi[128][40];
    __shared__ __align__(16) __nv_bfloat16 As_lo[128][40];
    __shared__ __align__(16) __nv_bfloat16 Bt_hi[128][40];
    __shared__ __align__(16) __nv_bfloat16 Bt_lo[128][40];
    __shared__ float s0part[2][128];

    const int t = threadIdx.x;
    const int warp = t >> 5, lane = t & 31;
    const int warpM = warp >> 1, warpN = warp & 1;
    const int row0 = blockIdx.x * 128;
    const int lq = lane >> 2;       // 0..7
    const int lr = lane & 3;        // 0..3

    float acc[2][8][4];
#pragma unroll
    for (int mt = 0; mt < 2; mt++)
#pragma unroll
        for (int nt = 0; nt < 8; nt++)
#pragma unroll
            for (int r = 0; r < 4; r++) acc[mt][nt][r] = 0.f;

    for (int kc = 0; kc < 4; kc++) {
        // --- pure bf16 uint4 copies into smem (no conversion) ---
#pragma unroll
        for (int it = 0; it < 2; it++) {
            int idx = t + it*256;            // 0..511: row = idx/4, kq = (idx%4)*8
            int row = idx >> 2;
            int kq  = (idx & 3) * 8;
            size_t ga = (size_t)(row0 + row)*128 + kc*32 + kq;
            *(uint4*)&As_hi[row][kq] = *(const uint4*)(A_hi + ga);
            *(uint4*)&As_lo[row][kq] = *(const uint4*)(A_lo + ga);
            size_t gb = (size_t)row*128 + kc*32 + kq;   // Wt[n][k]
            *(uint4*)&Bt_hi[row][kq] = *(const uint4*)(Wt_hi + gb);
            *(uint4*)&Bt_lo[row][kq] = *(const uint4*)(Wt_lo + gb);
        }
        __syncthreads();

#pragma unroll
        for (int ks = 0; ks < 2; ks++) {
            const int kb = ks * 16;
            unsigned a_hi[2][4], a_lo[2][4], b_hi[8][2], b_lo[8][2];
#pragma unroll
            for (int mt = 0; mt < 2; mt++) {
                int m = warpM*32 + mt*16 + lq;
                a_hi[mt][0] = *(const unsigned*)&As_hi[m    ][kb + 2*lr];
                a_hi[mt][1] = *(const unsigned*)&As_hi[m + 8][kb + 2*lr];
                a_hi[mt][2] = *(const unsigned*)&As_hi[m    ][kb + 2*lr + 8];
                a_hi[mt][3] = *(const unsigned*)&As_hi[m + 8][kb + 2*lr + 8];
                a_lo[mt][0] = *(const unsigned*)&As_lo[m    ][kb + 2*lr];
                a_lo[mt][1] = *(const unsigned*)&As_lo[m + 8][kb + 2*lr];
                a_lo[mt][2] = *(const unsigned*)&As_lo[m    ][kb + 2*lr + 8];
                a_lo[mt][3] = *(const unsigned*)&As_lo[m + 8][kb + 2*lr + 8];
            }
#pragma unroll
            for (int nt = 0; nt < 8; nt++) {
                int n = warpN*64 + nt*8 + lq;
                b_hi[nt][0] = *(const unsigned*)&Bt_hi[n][kb + 2*lr];
                b_hi[nt][1] = *(const unsigned*)&Bt_hi[n][kb + 2*lr + 8];
                b_lo[nt][0] = *(const unsigned*)&Bt_lo[n][kb + 2*lr];
                b_lo[nt][1] = *(const unsigned*)&Bt_lo[n][kb + 2*lr + 8];
            }
#pragma unroll
            for (int mt = 0; mt < 2; mt++)
#pragma unroll
                for (int nt = 0; nt < 8; nt++) {
                    mma_bf16(acc[mt][nt], a_hi[mt], b_hi[nt]);
                    mma_bf16(acc[mt][nt], a_lo[mt], b_hi[nt]);
                    mma_bf16(acc[mt][nt], a_hi[mt], b_lo[nt]);
                }
        }
        __syncthreads();
    }

    // --- epilogue: bias + relu + store + fused s0 = H.Ws ---
    float pacc[2][2] = {{0.f,0.f},{0.f,0.f}};
#pragma unroll
    for (int nt = 0; nt < 8; nt++) {
        int n0 = warpN*64 + nt*8 + 2*lr;
        float bb0 = __ldg(bias + n0), bb1 = __ldg(bias + n0 + 1);
        float ww0 = __ldg(Ws + n0),   ww1 = __ldg(Ws + n0 + 1);
#pragma unroll
        for (int mt = 0; mt < 2; mt++) {
            int r0 = warpM*32 + mt*16 + lq;
            float v0 = fmaxf(acc[mt][nt][0] + bb0, 0.f);
            float v1 = fmaxf(acc[mt][nt][1] + bb1, 0.f);
            float v2 = fmaxf(acc[mt][nt][2] + bb0, 0.f);
            float v3 = fmaxf(acc[mt][nt][3] + bb1, 0.f);
            *(float2*)(C + (size_t)(row0 + r0)*128 + n0)     = make_float2(v0, v1);
            *(float2*)(C + (size_t)(row0 + r0 + 8)*128 + n0) = make_float2(v2, v3);
            pacc[mt][0] += v0*ww0 + v1*ww1;
            pacc[mt][1] += v2*ww0 + v3*ww1;
        }
    }
#pragma unroll
    for (int mt = 0; mt < 2; mt++)
#pragma unroll
        for (int h = 0; h < 2; h++) {
            float p = pacc[mt][h];
            p += __shfl_xor_sync(0xFFFFFFFFu, p, 1);
            p += __shfl_xor_sync(0xFFFFFFFFu, p, 2);
            if (lr == 0) s0part[warpN][warpM*32 + mt*16 + lq + h*8] = p;
        }
    __syncthreads();
    if (t < 128) s0[row0 + t] = s0part[0][t] + s0part[1][t];
}

// =====================================================================
// Fused score-GCN + per-graph exact top-k (bitonic)
// =====================================================================
template<int NPG>
__global__ void k_topk(const int* __restrict__ cnt, const int* __restrict__ off,
                       const int* __restrict__ csr_src, const float* __restrict__ csr_w,
                       const float* __restrict__ s0, const float* __restrict__ bs,
                       int* __restrict__ topi, float* __restrict__ topt,
                       int* __restrict__ newidx) {
    constexpr int K = NPG/2;
    __shared__ unsigned long long keys[NPG];
    __shared__ float s_sc[NPG];
    int b = blockIdx.x, i = threadIdx.x;
    int gi = b*NPG + i;
    int c = cnt[gi], o = off[gi];
    float acc = bs[0] + s0[gi] / ((float)c + 1.f);
    float acc1 = 0.f, acc2 = 0.f, acc3 = 0.f;
    int j = 0;
    for (; j + 4 <= c; j += 4) {
        float w0 = csr_w[o+j],   w1 = csr_w[o+j+1];
        float w2 = csr_w[o+j+2], w3 = csr_w[o+j+3];
        int   n0 = csr_src[o+j],   n1 = csr_src[o+j+1];
        int   n2 = csr_src[o+j+2], n3 = csr_src[o+j+3];
        acc  += w0 * s0[n0];
        acc1 += w1 * s0[n1];
        acc2 += w2 * s0[n2];
        acc3 += w3 * s0[n3];
    }
    for (; j < c; j++) acc += csr_w[o+j] * s0[csr_src[o+j]];
    acc += acc1 + acc2 + acc3;
    s_sc[i] = acc;
    unsigned u  = __float_as_uint(acc);
    unsigned ou = u ^ ((u & 0x80000000u) ? 0xFFFFFFFFu : 0x80000000u);
    keys[i] = ((unsigned long long)(~ou) << 32) | (unsigned)i;
    __syncthreads();
    for (int kk = 2; kk <= NPG; kk <<= 1) {
        for (int j2 = kk >> 1; j2 > 0; j2 >>= 1) {
            int ixj = i ^ j2;
            if (ixj > i) {
                bool up = ((i & kk) == 0);
                unsigned long long a = keys[i], cc = keys[ixj];
                if ((a > cc) == up) { keys[i] = cc; keys[ixj] = a; }
            }
            __syncthreads();
        }
    }
    int idx = (int)(keys[i] & 0xFFFFFFFFull);
    if (i < K) {
        topi[b*K + i] = idx;
        topt[b*K + i] = tanhf(s_sc[idx]);
        newidx[b*NPG + idx] = b*K + i;
    } else {
        newidx[b*NPG + idx] = -1;
    }
}

// =====================================================================
// Fused gather*tanh + readout (max / mean), writes xnew for next stage
// =====================================================================
template<int NPG, int ACCUM>
__global__ __launch_bounds__(128)
void k_xr(const float* __restrict__ H, const int* __restrict__ topi,
          const float* __restrict__ topt, float* __restrict__ xnew,
          float* __restrict__ out) {
    constexpr int K = NPG/2;
    __shared__ int   s_old[K];
    __shared__ float s_t  [K];
    int b = blockIdx.x, cth = threadIdx.x;
    for (int j = cth; j < K; j += 128) { s_old[j] = topi[b*K + j]; s_t[j] = topt[b*K + j]; }
    __syncthreads();
    float mx = -3.402823466e38f, sm = 0.f;
#pragma unroll 4
    for (int j = 0; j < K; j++) {
        float v = H[(size_t)(b*NPG + s_old[j])*128 + cth] * s_t[j];
        xnew[(size_t)(b*K + j)*128 + cth] = v;
        mx = fmaxf(mx, v); sm += v;
    }
    if (ACCUM) {
        out[b*256 + cth]       += mx;
        out[b*256 + 128 + cth] += sm / (float)K;
    } else {
        out[b*256 + cth]       = mx;
        out[b*256 + 128 + cth] = sm / (float)K;
    }
}

// =====================================================================
extern "C" void kernel_launch(void* const* d_in, const int* in_sizes, int n_in,
                              void* d_out, int out_size) {
    const float* x   = (const float*)d_in[0];
    const int*   ei  = (const int*)  d_in[1];
    const float* W1  = (const float*)d_in[3];
    const float* b1  = (const float*)d_in[4];
    const float* Ws1 = (const float*)d_in[5];
    const float* bs1 = (const float*)d_in[6];
    const float* W2  = (const float*)d_in[7];
    const float* b2  = (const float*)d_in[8];
    const float* Ws2 = (const float*)d_in[9];
    const float* bs2 = (const float*)d_in[10];
    const float* W3  = (const float*)d_in[11];
    const float* b3  = (const float*)d_in[12];
    const float* Ws3 = (const float*)d_in[13];
    const float* bs3 = (const float*)d_in[14];
    float* out = (float*)d_out;

    __nv_bfloat16 *xah, *xal, *wth, *wtl;
    float *bufB, *bufC, *s0p, *csrw, *topt;
    int *srcp, *dstp, *csrs, *cntp, *offp, *topip, *newip;
    cudaGetSymbolAddress((void**)&xah,   g_Xa_hi);
    cudaGetSymbolAddress((void**)&xal,   g_Xa_lo);
    cudaGetSymbolAddress((void**)&wth,   g_Wt_hi);
    cudaGetSymbolAddress((void**)&wtl,   g_Wt_lo);
    cudaGetSymbolAddress((void**)&bufB,  g_bufB);
    cudaGetSymbolAddress((void**)&bufC,  g_bufC);
    cudaGetSymbolAddress((void**)&s0p,   g_s0);
    cudaGetSymbolAddress((void**)&csrw,  g_csr_w);
    cudaGetSymbolAddress((void**)&topt,  g_topt);
    cudaGetSymbolAddress((void**)&srcp,  g_src);
    cudaGetSymbolAddress((void**)&dstp,  g_dst);
    cudaGetSymbolAddress((void**)&csrs,  g_csr_src);
    cudaGetSymbolAddress((void**)&cntp,  g_cnt);
    cudaGetSymbolAddress((void**)&offp,  g_off);
    cudaGetSymbolAddress((void**)&topip, g_topi);
    cudaGetSymbolAddress((void**)&newip, g_newidx);

    const int* ei_src = ei;
    const int* ei_dst = ei + ETOT;

    // ---------------- stage 1: n=512, k=256 ----------------
    {
        const int NT = BGR*512;
        k_prep<512,0,0><<<BGR+1,512>>>(ei_src, ei_dst, newip, srcp, dstp,
                                       cntp, offp, csrs, csrw, W1, wth, wtl);
        k_agg <<<NT/8,256>>>(x, cntp, offp, csrs, csrw, xah, xal, NT);
        k_gemm_tc<<<NT/128,256>>>(xah, xal, wth, wtl, b1, Ws1, bufB, s0p);
        k_topk<512><<<BGR,512>>>(cntp, offp, csrs, csrw, s0p, bs1, topip, topt, newip);
        k_xr<512,0><<<BGR,128>>>(bufB, topip, topt, bufC, out);
    }
    // ---------------- stage 2: n=256, k=128 ----------------
    {
        const int NT = BGR*256;
        k_prep<256,1,1><<<BGR+1,512>>>(ei_src, ei_dst, newip, srcp, dstp,
                                       cntp, offp, csrs, csrw, W2, wth, wtl);
        k_agg <<<NT/8,256>>>(bufC, cntp, offp, csrs, csrw, xah, xal, NT);
        k_gemm_tc<<<NT/128,256>>>(xah, xal, wth, wtl, b2, Ws2, bufB, s0p);
        k_topk<256><<<BGR,256>>>(cntp, offp, csrs, csrw, s0p, bs2, topip, topt, newip);
        k_xr<256,1><<<BGR,128>>>(bufB, topip, topt, bufC, out);
    }
    // ---------------- stage 3: n=128, k=64 ----------------
    {
        const int NT = BGR*128;
        k_prep<128,1,0><<<BGR+1,512>>>(srcp, dstp, newip, srcp, dstp,
                                       cntp, offp, csrs, csrw, W3, wth, wtl);
        k_agg <<<NT/8,256>>>(bufC, cntp, offp, csrs, csrw, xah, xal, NT);
        k_gemm_tc<<<NT/128,256>>>(xah, xal, wth, wtl, b3, Ws3, bufB, s0p);
        k_topk<128><<<BGR,128>>>(cntp, offp, csrs, csrw, s0p, bs3, topip, topt, newip);
        k_xr<128,1><<<BGR,128>>>(bufB, topip, topt, bufC, out);
    }
}

// round 6
// speedup vs baseline: 1.2826x; 1.0277x over previous
#include <cuda_runtime.h>
#include <cuda_bf16.h>
#include <cstdint>

#define BGR   128          // graphs
#define EPG   4096         // edges per graph
#define ETOT  (BGR*EPG)    // 524288 edges
#define FDIM  128
#define NTMAX (BGR*512)    // 65536 max nodes

// ---------------- device scratch ----------------
__device__ __nv_bfloat16 g_Xa_hi[NTMAX*FDIM];   // aggregated input, split bf16
__device__ __nv_bfloat16 g_Xa_lo[NTMAX*FDIM];
__device__ __nv_bfloat16 g_Wt_hi[FDIM*FDIM];    // W transposed [n][k], split bf16
__device__ __nv_bfloat16 g_Wt_lo[FDIM*FDIM];
__device__ float g_bufB[NTMAX*FDIM];   // H  (post-GEMM features)
__device__ float g_bufC[NTMAX*FDIM];   // xnew (next-stage input)
__device__ float g_s0   [NTMAX];
__device__ int   g_src[ETOT];
__device__ int   g_dst[ETOT];
__device__ int   g_csr_src[ETOT];
__device__ float g_csr_w [ETOT];
__device__ int   g_cnt   [NTMAX];
__device__ int   g_off   [NTMAX];
__device__ int   g_newidx[NTMAX];

// =====================================================================
// k_pa: fused per-graph prep (remap+mask+count+dinv+scan+CSR in smem)
//       followed by in-block aggregation Xa = (self + neighbors) -> bf16
// Extra block (b == BGR) converts W -> transposed split-bf16.
// =====================================================================
template<int NPG, int REMAP, int WRITEBACK>
__global__ __launch_bounds__(512)
void k_pa(const int* __restrict__ esrc, const int* __restrict__ edst,
          const int* __restrict__ newidx,
          int* __restrict__ osrc, int* __restrict__ odst,
          int* __restrict__ cnt_g, int* __restrict__ off_g,
          int* __restrict__ csr_src_g, float* __restrict__ csr_w_g,
          const float* __restrict__ X,
          __nv_bfloat16* __restrict__ Xa_hi, __nv_bfloat16* __restrict__ Xa_lo,
          const float* __restrict__ W,
          __nv_bfloat16* __restrict__ Wt_hi, __nv_bfloat16* __restrict__ Wt_lo) {
    const int b = blockIdx.x, t = threadIdx.x;
    if (b == BGR) {
        // transpose + split W[128k][128n] -> Wt[n][k]
#pragma unroll
        for (int it = 0; it < 32; it++) {
            int idx = t + it*512;
            int n = idx >> 7, k = idx & 127;
            float v = W[k*128 + n];
            __nv_bfloat16 h = __float2bfloat16(v);
            Wt_hi[idx] = h;
            Wt_lo[idx] = __float2bfloat16(v - __bfloat162float(h));
        }
        return;
    }
    __shared__ unsigned short s_src[EPG];   // local src per csr slot
    __shared__ float          s_w  [EPG];
    __shared__ int   s_cnt [NPG];
    __shared__ int   s_cur [NPG];
    __shared__ int   s_offl[NPG];
    __shared__ float s_dinv[NPG];
    const int ebase = b * EPG;
    const int nbase = b * NPG;
    if (t < NPG) s_cnt[t] = 0;
    __syncthreads();

    int ls[8], ldst[8];
#pragma unroll
    for (int u = 0; u < 8; u++) {
        int e = ebase + u*512 + t;
        int s = esrc[e], d = edst[e];
        if (REMAP) {
            if (d >= 0) {
                int ns = newidx[s], nd = newidx[d];
                if (ns < 0 || nd < 0) d = -1;
                else { s = ns; d = nd; }
            }
        }
        if (WRITEBACK) { osrc[e] = s; odst[e] = d; }
        if (d >= 0) {
            ls[u]   = s - nbase;
            ldst[u] = d - nbase;
            atomicAdd(&s_cnt[ldst[u]], 1);
        } else ldst[u] = -1;
    }
    __syncthreads();

    int c = (t < NPG) ? s_cnt[t] : 0;
    if (t < NPG) {
        cnt_g[nbase + t] = c;
        s_dinv[t] = rsqrtf((float)c + 1.f);
        s_cur[t]  = c;
    }
    __syncthreads();
    for (int sft = 1; sft < NPG; sft <<= 1) {
        int add = (t >= sft && t < NPG) ? s_cur[t - sft] : 0;
        __syncthreads();
        if (t < NPG) s_cur[t] += add;
        __syncthreads();
    }
    if (t < NPG) {
        int o = s_cur[t] - c;            // exclusive prefix (local)
        off_g[nbase + t] = ebase + o;
        s_offl[t] = o;
        s_cur[t]  = o;                   // cursor
    }
    __syncthreads();

#pragma unroll
    for (int u = 0; u < 8; u++) {
        if (ldst[u] >= 0) {
            int pos = atomicAdd(&s_cur[ldst[u]], 1);
            float w = s_dinv[ls[u]] * s_dinv[ldst[u]];
            s_src[pos] = (unsigned short)ls[u];
            s_w  [pos] = w;
            csr_src_g[ebase + pos] = nbase + ls[u];
            csr_w_g  [ebase + pos] = w;
        }
    }
    __syncthreads();

    // ---------------- aggregation phase (16 warps over NPG nodes) ----
    const int warp = t >> 5, lane = t & 31;
    for (int node = warp; node < NPG; node += 16) {
        int cc = s_cnt[node], o = s_offl[node];
        float self = 1.f / ((float)cc + 1.f);
        size_t gi = (size_t)(nbase + node)*128 + lane*4;
        float4 hv = *(const float4*)(X + gi);
        float4 a0 = make_float4(self*hv.x, self*hv.y, self*hv.z, self*hv.w);
        float4 a1 = make_float4(0,0,0,0), a2 = make_float4(0,0,0,0), a3 = make_float4(0,0,0,0);
        int j = 0;
        for (; j + 4 <= cc; j += 4) {
            int   n0 = s_src[o+j],   n1 = s_src[o+j+1];
            int   n2 = s_src[o+j+2], n3 = s_src[o+j+3];
            float w0 = s_w[o+j],   w1 = s_w[o+j+1];
            float w2 = s_w[o+j+2], w3 = s_w[o+j+3];
            float4 h0 = *(const float4*)(X + (size_t)(nbase+n0)*128 + lane*4);
            float4 h1 = *(const float4*)(X + (size_t)(nbase+n1)*128 + lane*4);
            float4 h2 = *(const float4*)(X + (size_t)(nbase+n2)*128 + lane*4);
            float4 h3 = *(const float4*)(X + (size_t)(nbase+n3)*128 + lane*4);
            a0.x += w0*h0.x; a0.y += w0*h0.y; a0.z += w0*h0.z; a0.w += w0*h0.w;
            a1.x += w1*h1.x; a1.y += w1*h1.y; a1.z += w1*h1.z; a1.w += w1*h1.w;
            a2.x += w2*h2.x; a2.y += w2*h2.y; a2.z += w2*h2.z; a2.w += w2*h2.w;
            a3.x += w3*h3.x; a3.y += w3*h3.y; a3.z += w3*h3.z; a3.w += w3*h3.w;
        }
        for (; j < cc; j++) {
            int s = s_src[o+j]; float w = s_w[o+j];
            float4 hs = *(const float4*)(X + (size_t)(nbase+s)*128 + lane*4);
            a0.x += w*hs.x; a0.y += w*hs.y; a0.z += w*hs.z; a0.w += w*hs.w;
        }
        a0.x += a1.x + a2.x + a3.x;
        a0.y += a1.y + a2.y + a3.y;
        a0.z += a1.z + a2.z + a3.z;
        a0.w += a1.w + a2.w + a3.w;
        float f[4] = {a0.x, a0.y, a0.z, a0.w};
        __nv_bfloat16 hi4[4], lo4[4];
#pragma unroll
        for (int e = 0; e < 4; e++) {
            hi4[e] = __float2bfloat16(f[e]);
            lo4[e] = __float2bfloat16(f[e] - __bfloat162float(hi4[e]));
        }
        *(uint2*)(Xa_hi + gi) = *(uint2*)hi4;
        *(uint2*)(Xa_lo + gi) = *(uint2*)lo4;
    }
}

// =====================================================================
// Tensor-core GEMM (split-bf16 operands preconverted; 3 MMA terms):
//   H[M,128] = relu(Xa @ W + b); epilogue also computes s0 = H.Ws
// =====================================================================
__device__ __forceinline__ void mma_bf16(float* d, const unsigned* a, const unsigned* b) {
    asm volatile(
        "mma.sync.aligned.m16n8k16.row.col.f32.bf16.bf16.f32 "
        "{%0,%1,%2,%3}, {%4,%5,%6,%7}, {%8,%9}, {%0,%1,%2,%3};\n"
        : "+f"(d[0]), "+f"(d[1]), "+f"(d[2]), "+f"(d[3])
        : "r"(a[0]), "r"(a[1]), "r"(a[2]), "r"(a[3]), "r"(b[0]), "r"(b[1]));
}

__global__ __launch_bounds__(256)
void k_gemm_tc(const __nv_bfloat16* __restrict__ A_hi,
               const __nv_bfloat16* __restrict__ A_lo,
               const __nv_bfloat16* __restrict__ Wt_hi,
               const __nv_bfloat16* __restrict__ Wt_lo,
               const float* __restrict__ bias, const float* __restrict__ Ws,
               float* __restrict__ C, float* __restrict__ s0) {
    __shared__ __align__(16) __nv_bfloat16 As_hi[128][40];
    __shared__ __align__(16) __nv_bfloat16 As_lo[128][40];
    __shared__ __align__(16) __nv_bfloat16 Bt_hi[128][40];
    __shared__ __align__(16) __nv_bfloat16 Bt_lo[128][40];
    __shared__ float s0part[2][128];

    const int t = threadIdx.x;
    const int warp = t >> 5, lane = t & 31;
    const int warpM = warp >> 1, warpN = warp & 1;
    const int row0 = blockIdx.x * 128;
    const int lq = lane >> 2;
    const int lr = lane & 3;

    float acc[2][8][4];
#pragma unroll
    for (int mt = 0; mt < 2; mt++)
#pragma unroll
        for (int nt = 0; nt < 8; nt++)
#pragma unroll
            for (int r = 0; r < 4; r++) acc[mt][nt][r] = 0.f;

    for (int kc = 0; kc < 4; kc++) {
#pragma unroll
        for (int it = 0; it < 2; it++) {
            int idx = t + it*256;
            int row = idx >> 2;
            int kq  = (idx & 3) * 8;
            size_t ga = (size_t)(row0 + row)*128 + kc*32 + kq;
            *(uint4*)&As_hi[row][kq] = *(const uint4*)(A_hi + ga);
            *(uint4*)&As_lo[row][kq] = *(const uint4*)(A_lo + ga);
            size_t gb = (size_t)row*128 + kc*32 + kq;
            *(uint4*)&Bt_hi[row][kq] = *(const uint4*)(Wt_hi + gb);
            *(uint4*)&Bt_lo[row][kq] = *(const uint4*)(Wt_lo + gb);
        }
        __syncthreads();

#pragma unroll
        for (int ks = 0; ks < 2; ks++) {
            const int kb = ks * 16;
            unsigned a_hi[2][4], a_lo[2][4], b_hi[8][2], b_lo[8][2];
#pragma unroll
            for (int mt = 0; mt < 2; mt++) {
                int m = warpM*32 + mt*16 + lq;
                a_hi[mt][0] = *(const unsigned*)&As_hi[m    ][kb + 2*lr];
                a_hi[mt][1] = *(const unsigned*)&As_hi[m + 8][kb + 2*lr];
                a_hi[mt][2] = *(const unsigned*)&As_hi[m    ][kb + 2*lr + 8];
                a_hi[mt][3] = *(const unsigned*)&As_hi[m + 8][kb + 2*lr + 8];
                a_lo[mt][0] = *(const unsigned*)&As_lo[m    ][kb + 2*lr];
                a_lo[mt][1] = *(const unsigned*)&As_lo[m + 8][kb + 2*lr];
                a_lo[mt][2] = *(const unsigned*)&As_lo[m    ][kb + 2*lr + 8];
                a_lo[mt][3] = *(const unsigned*)&As_lo[m + 8][kb + 2*lr + 8];
            }
#pragma unroll
            for (int nt = 0; nt < 8; nt++) {
                int n = warpN*64 + nt*8 + lq;
                b_hi[nt][0] = *(const unsigned*)&Bt_hi[n][kb + 2*lr];
                b_hi[nt][1] = *(const unsigned*)&Bt_hi[n][kb + 2*lr + 8];
                b_lo[nt][0] = *(const unsigned*)&Bt_lo[n][kb + 2*lr];
                b_lo[nt][1] = *(const unsigned*)&Bt_lo[n][kb + 2*lr + 8];
            }
#pragma unroll
            for (int mt = 0; mt < 2; mt++)
#pragma unroll
                for (int nt = 0; nt < 8; nt++) {
                    mma_bf16(acc[mt][nt], a_hi[mt], b_hi[nt]);
                    mma_bf16(acc[mt][nt], a_lo[mt], b_hi[nt]);
                    mma_bf16(acc[mt][nt], a_hi[mt], b_lo[nt]);
                }
        }
        __syncthreads();
    }

    float pacc[2][2] = {{0.f,0.f},{0.f,0.f}};
#pragma unroll
    for (int nt = 0; nt < 8; nt++) {
        int n0 = warpN*64 + nt*8 + 2*lr;
        float bb0 = __ldg(bias + n0), bb1 = __ldg(bias + n0 + 1);
        float ww0 = __ldg(Ws + n0),   ww1 = __ldg(Ws + n0 + 1);
#pragma unroll
        for (int mt = 0; mt < 2; mt++) {
            int r0 = warpM*32 + mt*16 + lq;
            float v0 = fmaxf(acc[mt][nt][0] + bb0, 0.f);
            float v1 = fmaxf(acc[mt][nt][1] + bb1, 0.f);
            float v2 = fmaxf(acc[mt][nt][2] + bb0, 0.f);
            float v3 = fmaxf(acc[mt][nt][3] + bb1, 0.f);
            *(float2*)(C + (size_t)(row0 + r0)*128 + n0)     = make_float2(v0, v1);
            *(float2*)(C + (size_t)(row0 + r0 + 8)*128 + n0) = make_float2(v2, v3);
            pacc[mt][0] += v0*ww0 + v1*ww1;
            pacc[mt][1] += v2*ww0 + v3*ww1;
        }
    }
#pragma unroll
    for (int mt = 0; mt < 2; mt++)
#pragma unroll
        for (int h = 0; h < 2; h++) {
            float p = pacc[mt][h];
            p += __shfl_xor_sync(0xFFFFFFFFu, p, 1);
            p += __shfl_xor_sync(0xFFFFFFFFu, p, 2);
            if (lr == 0) s0part[warpN][warpM*32 + mt*16 + lq + h*8] = p;
        }
    __syncthreads();
    if (t < 128) s0[row0 + t] = s0part[0][t] + s0part[1][t];
}

// =====================================================================
// k_txr: fused score-GCN + hybrid bitonic top-k + gather*tanh + readout
// =====================================================================
template<int NPG, int ACCUM>
__global__ void k_txr(const int* __restrict__ cnt, const int* __restrict__ off,
                      const int* __restrict__ csr_src, const float* __restrict__ csr_w,
                      const float* __restrict__ s0, const float* __restrict__ bs,
                      int* __restrict__ newidx,
                      const float* __restrict__ H, float* __restrict__ xnew,
                      float* __restrict__ out) {
    constexpr int K = NPG/2;
    constexpr int G = NPG/128;           // readout row-groups
    __shared__ unsigned long long keys[NPG];
    __shared__ float s_s0l[NPG];
    __shared__ float s_sc [NPG];
    __shared__ int   s_old[K];
    __shared__ float s_t  [K];
    __shared__ float r_mx [NPG];
    __shared__ float r_sm [NPG];
    const int b = blockIdx.x, i = threadIdx.x;
    const int nbase = b*NPG;
    const int gi = nbase + i;

    // ---- score GCN (s0 staged in smem) ----
    s_s0l[i] = s0[gi];
    __syncthreads();
    int c = cnt[gi], o = off[gi];
    float acc = bs[0] + s_s0l[i] / ((float)c + 1.f);
    float acc1 = 0.f, acc2 = 0.f, acc3 = 0.f;
    int j = 0;
    for (; j + 4 <= c; j += 4) {
        int   n0 = csr_src[o+j] - nbase,   n1 = csr_src[o+j+1] - nbase;
        int   n2 = csr_src[o+j+2] - nbase, n3 = csr_src[o+j+3] - nbase;
        float w0 = csr_w[o+j],   w1 = csr_w[o+j+1];
        float w2 = csr_w[o+j+2], w3 = csr_w[o+j+3];
        acc  += w0 * s_s0l[n0];
        acc1 += w1 * s_s0l[n1];
        acc2 += w2 * s_s0l[n2];
        acc3 += w3 * s_s0l[n3];
    }
    for (; j < c; j++) acc += csr_w[o+j] * s_s0l[csr_src[o+j] - nbase];
    acc += acc1 + acc2 + acc3;
    s_sc[i] = acc;
    unsigned u  = __float_as_uint(acc);
    unsigned ou = u ^ ((u & 0x80000000u) ? 0xFFFFFFFFu : 0x80000000u);
    keys[i] = ((unsigned long long)(~ou) << 32) | (unsigned)i;  // asc => desc score, asc idx
    __syncthreads();

    // ---- hybrid bitonic sort: smem steps for j>=32, shfl for j<32 ----
    for (int kk = 2; kk <= NPG; kk <<= 1) {
        for (int js = kk >> 1; js >= 32; js >>= 1) {
            int ixj = i ^ js;
            if (ixj > i) {
                bool up = ((i & kk) == 0);
                unsigned long long a = keys[i], cc2 = keys[ixj];
                if ((a > cc2) == up) { keys[i] = cc2; keys[ixj] = a; }
            }
            __syncthreads();
        }
        {
            unsigned long long v = keys[i];
            const bool up = ((i & kk) == 0);
            int js0 = (kk >> 1) < 16 ? (kk >> 1) : 16;
            for (int js = js0; js > 0; js >>= 1) {
                unsigned long long p = __shfl_xor_sync(0xFFFFFFFFu, v, js);
                bool keepSmall = (((i & js) == 0) == up);
                if ((p < v) == keepSmall) v = p;
            }
            keys[i] = v;
        }
        __syncthreads();
    }

    // ---- topk outputs + newidx ----
    int idx = (int)(keys[i] & 0xFFFFFFFFull);
    if (i < K) {
        s_old[i] = idx;
        s_t[i]   = tanhf(s_sc[idx]);
        newidx[nbase + idx] = b*K + i;
    } else {
        newidx[nbase + idx] = -1;
    }
    __syncthreads();

    // ---- gather*tanh + readout (G row-groups of 128 columns) ----
    const int col = i & 127, g = i >> 7;
    float mx = -3.402823466e38f, sm = 0.f;
    for (int jr = g; jr < K; jr += G) {
        float v = H[(size_t)(nbase + s_old[jr])*128 + col] * s_t[jr];
        xnew[(size_t)(b*K + jr)*128 + col] = v;
        mx = fmaxf(mx, v); sm += v;
    }
    if (G > 1) {
        r_mx[g*128 + col] = mx;
        r_sm[g*128 + col] = sm;
        __syncthreads();
        if (g == 0) {
#pragma unroll
            for (int gg = 1; gg < G; gg++) {
                mx = fmaxf(mx, r_mx[gg*128 + col]);
                sm += r_sm[gg*128 + col];
            }
        }
    }
    if (g == 0) {
        if (ACCUM) {
            out[b*256 + col]       += mx;
            out[b*256 + 128 + col] += sm / (float)K;
        } else {
            out[b*256 + col]       = mx;
            out[b*256 + 128 + col] = sm / (float)K;
        }
    }
}

// =====================================================================
extern "C" void kernel_launch(void* const* d_in, const int* in_sizes, int n_in,
                              void* d_out, int out_size) {
    const float* x   = (const float*)d_in[0];
    const int*   ei  = (const int*)  d_in[1];
    const float* W1  = (const float*)d_in[3];
    const float* b1  = (const float*)d_in[4];
    const float* Ws1 = (const float*)d_in[5];
    const float* bs1 = (const float*)d_in[6];
    const float* W2  = (const float*)d_in[7];
    const float* b2  = (const float*)d_in[8];
    const float* Ws2 = (const float*)d_in[9];
    const float* bs2 = (const float*)d_in[10];
    const float* W3  = (const float*)d_in[11];
    const float* b3  = (const float*)d_in[12];
    const float* Ws3 = (const float*)d_in[13];
    const float* bs3 = (const float*)d_in[14];
    float* out = (float*)d_out;

    __nv_bfloat16 *xah, *xal, *wth, *wtl;
    float *bufB, *bufC, *s0p, *csrw;
    int *srcp, *dstp, *csrs, *cntp, *offp, *newip;
    cudaGetSymbolAddress((void**)&xah,   g_Xa_hi);
    cudaGetSymbolAddress((void**)&xal,   g_Xa_lo);
    cudaGetSymbolAddress((void**)&wth,   g_Wt_hi);
    cudaGetSymbolAddress((void**)&wtl,   g_Wt_lo);
    cudaGetSymbolAddress((void**)&bufB,  g_bufB);
    cudaGetSymbolAddress((void**)&bufC,  g_bufC);
    cudaGetSymbolAddress((void**)&s0p,   g_s0);
    cudaGetSymbolAddress((void**)&csrw,  g_csr_w);
    cudaGetSymbolAddress((void**)&srcp,  g_src);
    cudaGetSymbolAddress((void**)&dstp,  g_dst);
    cudaGetSymbolAddress((void**)&csrs,  g_csr_src);
    cudaGetSymbolAddress((void**)&cntp,  g_cnt);
    cudaGetSymbolAddress((void**)&offp,  g_off);
    cudaGetSymbolAddress((void**)&newip, g_newidx);

    const int* ei_src = ei;
    const int* ei_dst = ei + ETOT;

    // ---------------- stage 1: n=512, k=256 ----------------
    {
        const int NT = BGR*512;
        k_pa<512,0,0><<<BGR+1,512>>>(ei_src, ei_dst, newip, srcp, dstp,
                                     cntp, offp, csrs, csrw,
                                     x, xah, xal, W1, wth, wtl);
        k_gemm_tc<<<NT/128,256>>>(xah, xal, wth, wtl, b1, Ws1, bufB, s0p);
        k_txr<512,0><<<BGR,512>>>(cntp, offp, csrs, csrw, s0p, bs1, newip,
                                  bufB, bufC, out);
    }
    // ---------------- stage 2: n=256, k=128 ----------------
    {
        const int NT = BGR*256;
        k_pa<256,1,1><<<BGR+1,512>>>(ei_src, ei_dst, newip, srcp, dstp,
                                     cntp, offp, csrs, csrw,
                                     bufC, xah, xal, W2, wth, wtl);
        k_gemm_tc<<<NT/128,256>>>(xah, xal, wth, wtl, b2, Ws2, bufB, s0p);
        k_txr<256,1><<<BGR,256>>>(cntp, offp, csrs, csrw, s0p, bs2, newip,
                                  bufB, bufC, out);
    }
    // ---------------- stage 3: n=128, k=64 ----------------
    {
        const int NT = BGR*128;
        k_pa<128,1,0><<<BGR+1,512>>>(srcp, dstp, newip, srcp, dstp,
                                     cntp, offp, csrs, csrw,
                                     bufC, xah, xal, W3, wth, wtl);
        k_gemm_tc<<<NT/128,256>>>(xah, xal, wth, wtl, b3, Ws3, bufB, s0p);
        k_txr<128,1><<<BGR,128>>>(cntp, offp, csrs, csrw, s0p, bs3, newip,
                                  bufB, bufC, out);
    }
}

// round 7
// speedup vs baseline: 1.7000x; 1.3254x over previous
#include <cuda_runtime.h>
#include <cuda_bf16.h>
#include <cstdint>

#define BGR   128          // graphs
#define EPG   4096         // edges per graph
#define ETOT  (BGR*EPG)    // 524288 edges
#define FDIM  128
#define NTMAX (BGR*512)    // 65536 max nodes

// ---------------- device scratch ----------------
__device__ __nv_bfloat16 g_Xa_hi[NTMAX*FDIM];   // aggregated input, split bf16
__device__ __nv_bfloat16 g_Xa_lo[NTMAX*FDIM];
__device__ __nv_bfloat16 g_Wt_hi[FDIM*FDIM];    // W transposed [n][k], split bf16
__device__ __nv_bfloat16 g_Wt_lo[FDIM*FDIM];
__device__ float g_bufB[NTMAX*FDIM];   // H  (post-GEMM features)
__device__ float g_bufC[NTMAX*FDIM];   // xnew (next-stage input)
__device__ float g_s0   [NTMAX];
__device__ int   g_src[ETOT];
__device__ int   g_dst[ETOT];
__device__ int   g_csr_src[ETOT];
__device__ float g_csr_w [ETOT];
__device__ int   g_cnt   [NTMAX];
__device__ int   g_off   [NTMAX];
__device__ int   g_newidx[NTMAX];

// =====================================================================
// k_pa: fused per-graph prep (remap+mask+count+dinv+warp-scan+CSR)
//       followed by in-block aggregation Xa -> split bf16.
// 1024 threads/block; extra block (b == BGR) converts W.
// =====================================================================
template<int NPG, int REMAP, int WRITEBACK>
__global__ __launch_bounds__(1024)
void k_pa(const int* __restrict__ esrc, const int* __restrict__ edst,
          const int* __restrict__ newidx,
          int* __restrict__ osrc, int* __restrict__ odst,
          int* __restrict__ cnt_g, int* __restrict__ off_g,
          int* __restrict__ csr_src_g, float* __restrict__ csr_w_g,
          const float* __restrict__ X,
          __nv_bfloat16* __restrict__ Xa_hi, __nv_bfloat16* __restrict__ Xa_lo,
          const float* __restrict__ W,
          __nv_bfloat16* __restrict__ Wt_hi, __nv_bfloat16* __restrict__ Wt_lo) {
    const int b = blockIdx.x, t = threadIdx.x;
    if (b == BGR) {
        // transpose + split W[128k][128n] -> Wt[n][k]
#pragma unroll
        for (int it = 0; it < 16; it++) {
            int idx = t + it*1024;
            int n = idx >> 7, k = idx & 127;
            float v = W[k*128 + n];
            __nv_bfloat16 h = __float2bfloat16(v);
            Wt_hi[idx] = h;
            Wt_lo[idx] = __float2bfloat16(v - __bfloat162float(h));
        }
        return;
    }
    __shared__ unsigned short s_src[EPG];   // local src per csr slot
    __shared__ float          s_w  [EPG];
    __shared__ int   s_cnt [NPG];
    __shared__ int   s_cur [NPG];
    __shared__ int   s_offl[NPG];
    __shared__ float s_dinv[NPG];
    __shared__ int   s_ws  [NPG/32];        // warp partial sums
    const int ebase = b * EPG;
    const int nbase = b * NPG;
    const int lane = t & 31, wid = t >> 5;
    if (t < NPG) s_cnt[t] = 0;
    __syncthreads();

    int ls[4], ldst[4];
#pragma unroll
    for (int u = 0; u < 4; u++) {
        int e = ebase + u*1024 + t;
        int s = esrc[e], d = edst[e];
        if (REMAP) {
            if (d >= 0) {
                int ns = newidx[s], nd = newidx[d];
                if (ns < 0 || nd < 0) d = -1;
                else { s = ns; d = nd; }
            }
        }
        if (WRITEBACK) { osrc[e] = s; odst[e] = d; }
        if (d >= 0) {
            ls[u]   = s - nbase;
            ldst[u] = d - nbase;
            atomicAdd(&s_cnt[ldst[u]], 1);
        } else ldst[u] = -1;
    }
    __syncthreads();

    // ---- two-level warp-shuffle exclusive scan over NPG counts ----
    int c = 0, vincl = 0;
    if (t < NPG) {
        c = s_cnt[t];
        vincl = c;
#pragma unroll
        for (int d = 1; d < 32; d <<= 1) {
            int nv = __shfl_up_sync(0xFFFFFFFFu, vincl, d);
            if (lane >= d) vincl += nv;
        }
        if (lane == 31) s_ws[wid] = vincl;
        cnt_g[nbase + t] = c;
        s_dinv[t] = rsqrtf((float)c + 1.f);
    }
    __syncthreads();
    if (t < 32) {
        constexpr int NW = NPG/32;
        int v = (t < NW) ? s_ws[t] : 0;
#pragma unroll
        for (int d = 1; d < 32; d <<= 1) {
            int nv = __shfl_up_sync(0xFFFFFFFFu, v, d);
            if (lane >= d) v += nv;
        }
        if (t < NW) s_ws[t] = v;        // inclusive warp-sum prefix
    }
    __syncthreads();
    if (t < NPG) {
        int base = (wid > 0) ? s_ws[wid - 1] : 0;
        int excl = base + vincl - c;
        off_g[nbase + t] = ebase + excl;
        s_offl[t] = excl;
        s_cur[t]  = excl;
    }
    __syncthreads();

#pragma unroll
    for (int u = 0; u < 4; u++) {
        if (ldst[u] >= 0) {
            int pos = atomicAdd(&s_cur[ldst[u]], 1);
            float w = s_dinv[ls[u]] * s_dinv[ldst[u]];
            s_src[pos] = (unsigned short)ls[u];
            s_w  [pos] = w;
            csr_src_g[ebase + pos] = nbase + ls[u];
            csr_w_g  [ebase + pos] = w;
        }
    }
    __syncthreads();

    // ---------------- aggregation phase (32 warps over NPG nodes) ----
    for (int node = wid; node < NPG; node += 32) {
        int cc = s_cnt[node], o = s_offl[node];
        float self = 1.f / ((float)cc + 1.f);
        size_t gi = (size_t)(nbase + node)*128 + lane*4;
        float4 hv = *(const float4*)(X + gi);
        float4 a0 = make_float4(self*hv.x, self*hv.y, self*hv.z, self*hv.w);
        float4 a1 = make_float4(0,0,0,0), a2 = make_float4(0,0,0,0), a3 = make_float4(0,0,0,0);
        int j = 0;
        for (; j + 4 <= cc; j += 4) {
            int   n0 = s_src[o+j],   n1 = s_src[o+j+1];
            int   n2 = s_src[o+j+2], n3 = s_src[o+j+3];
            float w0 = s_w[o+j],   w1 = s_w[o+j+1];
            float w2 = s_w[o+j+2], w3 = s_w[o+j+3];
            float4 h0 = *(const float4*)(X + (size_t)(nbase+n0)*128 + lane*4);
            float4 h1 = *(const float4*)(X + (size_t)(nbase+n1)*128 + lane*4);
            float4 h2 = *(const float4*)(X + (size_t)(nbase+n2)*128 + lane*4);
            float4 h3 = *(const float4*)(X + (size_t)(nbase+n3)*128 + lane*4);
            a0.x += w0*h0.x; a0.y += w0*h0.y; a0.z += w0*h0.z; a0.w += w0*h0.w;
            a1.x += w1*h1.x; a1.y += w1*h1.y; a1.z += w1*h1.z; a1.w += w1*h1.w;
            a2.x += w2*h2.x; a2.y += w2*h2.y; a2.z += w2*h2.z; a2.w += w2*h2.w;
            a3.x += w3*h3.x; a3.y += w3*h3.y; a3.z += w3*h3.z; a3.w += w3*h3.w;
        }
        for (; j < cc; j++) {
            int s = s_src[o+j]; float w = s_w[o+j];
            float4 hs = *(const float4*)(X + (size_t)(nbase+s)*128 + lane*4);
            a0.x += w*hs.x; a0.y += w*hs.y; a0.z += w*hs.z; a0.w += w*hs.w;
        }
        a0.x += a1.x + a2.x + a3.x;
        a0.y += a1.y + a2.y + a3.y;
        a0.z += a1.z + a2.z + a3.z;
        a0.w += a1.w + a2.w + a3.w;
        float f[4] = {a0.x, a0.y, a0.z, a0.w};
        __nv_bfloat16 hi4[4], lo4[4];
#pragma unroll
        for (int e = 0; e < 4; e++) {
            hi4[e] = __float2bfloat16(f[e]);
            lo4[e] = __float2bfloat16(f[e] - __bfloat162float(hi4[e]));
        }
        *(uint2*)(Xa_hi + gi) = *(uint2*)hi4;
        *(uint2*)(Xa_lo + gi) = *(uint2*)lo4;
    }
}

// =====================================================================
// Tensor-core GEMM (split-bf16 operands preconverted; 3 MMA terms):
//   H[M,128] = relu(Xa @ W + b); epilogue also computes s0 = H.Ws
// =====================================================================
__device__ __forceinline__ void mma_bf16(float* d, const unsigned* a, const unsigned* b) {
    asm volatile(
        "mma.sync.aligned.m16n8k16.row.col.f32.bf16.bf16.f32 "
        "{%0,%1,%2,%3}, {%4,%5,%6,%7}, {%8,%9}, {%0,%1,%2,%3};\n"
        : "+f"(d[0]), "+f"(d[1]), "+f"(d[2]), "+f"(d[3])
        : "r"(a[0]), "r"(a[1]), "r"(a[2]), "r"(a[3]), "r"(b[0]), "r"(b[1]));
}

__global__ __launch_bounds__(256)
void k_gemm_tc(const __nv_bfloat16* __restrict__ A_hi,
               const __nv_bfloat16* __restrict__ A_lo,
               const __nv_bfloat16* __restrict__ Wt_hi,
               const __nv_bfloat16* __restrict__ Wt_lo,
               const float* __restrict__ bias, const float* __restrict__ Ws,
               float* __restrict__ C, float* __restrict__ s0) {
    __shared__ __align__(16) __nv_bfloat16 As_hi[128][40];
    __shared__ __align__(16) __nv_bfloat16 As_lo[128][40];
    __shared__ __align__(16) __nv_bfloat16 Bt_hi[128][40];
    __shared__ __align__(16) __nv_bfloat16 Bt_lo[128][40];
    __shared__ float s0part[2][128];

    const int t = threadIdx.x;
    const int warp = t >> 5, lane = t & 31;
    const int warpM = warp >> 1, warpN = warp & 1;
    const int row0 = blockIdx.x * 128;
    const int lq = lane >> 2;
    const int lr = lane & 3;

    float acc[2][8][4];
#pragma unroll
    for (int mt = 0; mt < 2; mt++)
#pragma unroll
        for (int nt = 0; nt < 8; nt++)
#pragma unroll
            for (int r = 0; r < 4; r++) acc[mt][nt][r] = 0.f;

    for (int kc = 0; kc < 4; kc++) {
#pragma unroll
        for (int it = 0; it < 2; it++) {
            int idx = t + it*256;
            int row = idx >> 2;
            int kq  = (idx & 3) * 8;
            size_t ga = (size_t)(row0 + row)*128 + kc*32 + kq;
            *(uint4*)&As_hi[row][kq] = *(const uint4*)(A_hi + ga);
            *(uint4*)&As_lo[row][kq] = *(const uint4*)(A_lo + ga);
            size_t gb = (size_t)row*128 + kc*32 + kq;
            *(uint4*)&Bt_hi[row][kq] = *(const uint4*)(Wt_hi + gb);
            *(uint4*)&Bt_lo[row][kq] = *(const uint4*)(Wt_lo + gb);
        }
        __syncthreads();

#pragma unroll
        for (int ks = 0; ks < 2; ks++) {
            const int kb = ks * 16;
            unsigned a_hi[2][4], a_lo[2][4], b_hi[8][2], b_lo[8][2];
#pragma unroll
            for (int mt = 0; mt < 2; mt++) {
                int m = warpM*32 + mt*16 + lq;
                a_hi[mt][0] = *(const unsigned*)&As_hi[m    ][kb + 2*lr];
                a_hi[mt][1] = *(const unsigned*)&As_hi[m + 8][kb + 2*lr];
                a_hi[mt][2] = *(const unsigned*)&As_hi[m    ][kb + 2*lr + 8];
                a_hi[mt][3] = *(const unsigned*)&As_hi[m + 8][kb + 2*lr + 8];
                a_lo[mt][0] = *(const unsigned*)&As_lo[m    ][kb + 2*lr];
                a_lo[mt][1] = *(const unsigned*)&As_lo[m + 8][kb + 2*lr];
                a_lo[mt][2] = *(const unsigned*)&As_lo[m    ][kb + 2*lr + 8];
                a_lo[mt][3] = *(const unsigned*)&As_lo[m + 8][kb + 2*lr + 8];
            }
#pragma unroll
            for (int nt = 0; nt < 8; nt++) {
                int n = warpN*64 + nt*8 + lq;
                b_hi[nt][0] = *(const unsigned*)&Bt_hi[n][kb + 2*lr];
                b_hi[nt][1] = *(const unsigned*)&Bt_hi[n][kb + 2*lr + 8];
                b_lo[nt][0] = *(const unsigned*)&Bt_lo[n][kb + 2*lr];
                b_lo[nt][1] = *(const unsigned*)&Bt_lo[n][kb + 2*lr + 8];
            }
#pragma unroll
            for (int mt = 0; mt < 2; mt++)
#pragma unroll
                for (int nt = 0; nt < 8; nt++) {
                    mma_bf16(acc[mt][nt], a_hi[mt], b_hi[nt]);
                    mma_bf16(acc[mt][nt], a_lo[mt], b_hi[nt]);
                    mma_bf16(acc[mt][nt], a_hi[mt], b_lo[nt]);
                }
        }
        __syncthreads();
    }

    float pacc[2][2] = {{0.f,0.f},{0.f,0.f}};
#pragma unroll
    for (int nt = 0; nt < 8; nt++) {
        int n0 = warpN*64 + nt*8 + 2*lr;
        float bb0 = __ldg(bias + n0), bb1 = __ldg(bias + n0 + 1);
        float ww0 = __ldg(Ws + n0),   ww1 = __ldg(Ws + n0 + 1);
#pragma unroll
        for (int mt = 0; mt < 2; mt++) {
            int r0 = warpM*32 + mt*16 + lq;
            float v0 = fmaxf(acc[mt][nt][0] + bb0, 0.f);
            float v1 = fmaxf(acc[mt][nt][1] + bb1, 0.f);
            float v2 = fmaxf(acc[mt][nt][2] + bb0, 0.f);
            float v3 = fmaxf(acc[mt][nt][3] + bb1, 0.f);
            *(float2*)(C + (size_t)(row0 + r0)*128 + n0)     = make_float2(v0, v1);
            *(float2*)(C + (size_t)(row0 + r0 + 8)*128 + n0) = make_float2(v2, v3);
            pacc[mt][0] += v0*ww0 + v1*ww1;
            pacc[mt][1] += v2*ww0 + v3*ww1;
        }
    }
#pragma unroll
    for (int mt = 0; mt < 2; mt++)
#pragma unroll
        for (int h = 0; h < 2; h++) {
            float p = pacc[mt][h];
            p += __shfl_xor_sync(0xFFFFFFFFu, p, 1);
            p += __shfl_xor_sync(0xFFFFFFFFu, p, 2);
            if (lr == 0) s0part[warpN][warpM*32 + mt*16 + lq + h*8] = p;
        }
    __syncthreads();
    if (t < 128) s0[row0 + t] = s0part[0][t] + s0part[1][t];
}

// =====================================================================
// k_txr: fused score-GCN + hybrid bitonic top-k + gather*tanh + readout
// =====================================================================
template<int NPG, int ACCUM>
__global__ void k_txr(const int* __restrict__ cnt, const int* __restrict__ off,
                      const int* __restrict__ csr_src, const float* __restrict__ csr_w,
                      const float* __restrict__ s0, const float* __restrict__ bs,
                      int* __restrict__ newidx,
                      const float* __restrict__ H, float* __restrict__ xnew,
                      float* __restrict__ out) {
    constexpr int K = NPG/2;
    constexpr int G = NPG/128;           // readout row-groups
    __shared__ unsigned long long keys[NPG];
    __shared__ float s_s0l[NPG];
    __shared__ float s_sc [NPG];
    __shared__ int   s_old[K];
    __shared__ float s_t  [K];
    __shared__ float r_mx [NPG];
    __shared__ float r_sm [NPG];
    const int b = blockIdx.x, i = threadIdx.x;
    const int nbase = b*NPG;
    const int gi = nbase + i;

    // ---- score GCN (s0 staged in smem) ----
    s_s0l[i] = s0[gi];
    __syncthreads();
    int c = cnt[gi], o = off[gi];
    float acc = bs[0] + s_s0l[i] / ((float)c + 1.f);
    float acc1 = 0.f, acc2 = 0.f, acc3 = 0.f;
    int j = 0;
    for (; j + 4 <= c; j += 4) {
        int   n0 = csr_src[o+j] - nbase,   n1 = csr_src[o+j+1] - nbase;
        int   n2 = csr_src[o+j+2] - nbase, n3 = csr_src[o+j+3] - nbase;
        float w0 = csr_w[o+j],   w1 = csr_w[o+j+1];
        float w2 = csr_w[o+j+2], w3 = csr_w[o+j+3];
        acc  += w0 * s_s0l[n0];
        acc1 += w1 * s_s0l[n1];
        acc2 += w2 * s_s0l[n2];
        acc3 += w3 * s_s0l[n3];
    }
    for (; j < c; j++) acc += csr_w[o+j] * s_s0l[csr_src[o+j] - nbase];
    acc += acc1 + acc2 + acc3;
    s_sc[i] = acc;
    unsigned u  = __float_as_uint(acc);
    unsigned ou = u ^ ((u & 0x80000000u) ? 0xFFFFFFFFu : 0x80000000u);
    keys[i] = ((unsigned long long)(~ou) << 32) | (unsigned)i;  // asc => desc score, asc idx
    __syncthreads();

    // ---- hybrid bitonic sort: smem steps for j>=32, shfl for j<32 ----
    for (int kk = 2; kk <= NPG; kk <<= 1) {
        for (int js = kk >> 1; js >= 32; js >>= 1) {
            int ixj = i ^ js;
            if (ixj > i) {
                bool up = ((i & kk) == 0);
                unsigned long long a = keys[i], cc2 = keys[ixj];
                if ((a > cc2) == up) { keys[i] = cc2; keys[ixj] = a; }
            }
            __syncthreads();
        }
        {
            unsigned long long v = keys[i];
            const bool up = ((i & kk) == 0);
            int js0 = (kk >> 1) < 16 ? (kk >> 1) : 16;
            for (int js = js0; js > 0; js >>= 1) {
                unsigned long long p = __shfl_xor_sync(0xFFFFFFFFu, v, js);
                bool keepSmall = (((i & js) == 0) == up);
                if ((p < v) == keepSmall) v = p;
            }
            keys[i] = v;
        }
        __syncthreads();
    }

    // ---- topk outputs + newidx ----
    int idx = (int)(keys[i] & 0xFFFFFFFFull);
    if (i < K) {
        s_old[i] = idx;
        s_t[i]   = tanhf(s_sc[idx]);
        newidx[nbase + idx] = b*K + i;
    } else {
        newidx[nbase + idx] = -1;
    }
    __syncthreads();

    // ---- gather*tanh + readout (G row-groups of 128 columns) ----
    const int col = i & 127, g = i >> 7;
    float mx = -3.402823466e38f, sm = 0.f;
    for (int jr = g; jr < K; jr += G) {
        float v = H[(size_t)(nbase + s_old[jr])*128 + col] * s_t[jr];
        xnew[(size_t)(b*K + jr)*128 + col] = v;
        mx = fmaxf(mx, v); sm += v;
    }
    if (G > 1) {
        r_mx[g*128 + col] = mx;
        r_sm[g*128 + col] = sm;
        __syncthreads();
        if (g == 0) {
#pragma unroll
            for (int gg = 1; gg < G; gg++) {
                mx = fmaxf(mx, r_mx[gg*128 + col]);
                sm += r_sm[gg*128 + col];
            }
        }
    }
    if (g == 0) {
        if (ACCUM) {
            out[b*256 + col]       += mx;
            out[b*256 + 128 + col] += sm / (float)K;
        } else {
            out[b*256 + col]       = mx;
            out[b*256 + 128 + col] = sm / (float)K;
        }
    }
}

// =====================================================================
extern "C" void kernel_launch(void* const* d_in, const int* in_sizes, int n_in,
                              void* d_out, int out_size) {
    const float* x   = (const float*)d_in[0];
    const int*   ei  = (const int*)  d_in[1];
    const float* W1  = (const float*)d_in[3];
    const float* b1  = (const float*)d_in[4];
    const float* Ws1 = (const float*)d_in[5];
    const float* bs1 = (const float*)d_in[6];
    const float* W2  = (const float*)d_in[7];
    const float* b2  = (const float*)d_in[8];
    const float* Ws2 = (const float*)d_in[9];
    const float* bs2 = (const float*)d_in[10];
    const float* W3  = (const float*)d_in[11];
    const float* b3  = (const float*)d_in[12];
    const float* Ws3 = (const float*)d_in[13];
    const float* bs3 = (const float*)d_in[14];
    float* out = (float*)d_out;

    __nv_bfloat16 *xah, *xal, *wth, *wtl;
    float *bufB, *bufC, *s0p, *csrw;
    int *srcp, *dstp, *csrs, *cntp, *offp, *newip;
    cudaGetSymbolAddress((void**)&xah,   g_Xa_hi);
    cudaGetSymbolAddress((void**)&xal,   g_Xa_lo);
    cudaGetSymbolAddress((void**)&wth,   g_Wt_hi);
    cudaGetSymbolAddress((void**)&wtl,   g_Wt_lo);
    cudaGetSymbolAddress((void**)&bufB,  g_bufB);
    cudaGetSymbolAddress((void**)&bufC,  g_bufC);
    cudaGetSymbolAddress((void**)&s0p,   g_s0);
    cudaGetSymbolAddress((void**)&csrw,  g_csr_w);
    cudaGetSymbolAddress((void**)&srcp,  g_src);
    cudaGetSymbolAddress((void**)&dstp,  g_dst);
    cudaGetSymbolAddress((void**)&csrs,  g_csr_src);
    cudaGetSymbolAddress((void**)&cntp,  g_cnt);
    cudaGetSymbolAddress((void**)&offp,  g_off);
    cudaGetSymbolAddress((void**)&newip, g_newidx);

    const int* ei_src = ei;
    const int* ei_dst = ei + ETOT;

    // ---------------- stage 1: n=512, k=256 ----------------
    {
        const int NT = BGR*512;
        k_pa<512,0,0><<<BGR+1,1024>>>(ei_src, ei_dst, newip, srcp, dstp,
                                      cntp, offp, csrs, csrw,
                                      x, xah, xal, W1, wth, wtl);
        k_gemm_tc<<<NT/128,256>>>(xah, xal, wth, wtl, b1, Ws1, bufB, s0p);
        k_txr<512,0><<<BGR,512>>>(cntp, offp, csrs, csrw, s0p, bs1, newip,
                                  bufB, bufC, out);
    }
    // ---------------- stage 2: n=256, k=128 ----------------
    {
        const int NT = BGR*256;
        k_pa<256,1,1><<<BGR+1,1024>>>(ei_src, ei_dst, newip, srcp, dstp,
                                      cntp, offp, csrs, csrw,
                                      bufC, xah, xal, W2, wth, wtl);
        k_gemm_tc<<<NT/128,256>>>(xah, xal, wth, wtl, b2, Ws2, bufB, s0p);
        k_txr<256,1><<<BGR,256>>>(cntp, offp, csrs, csrw, s0p, bs2, newip,
                                  bufB, bufC, out);
    }
    // ---------------- stage 3: n=128, k=64 ----------------
    {
        const int NT = BGR*128;
        k_pa<128,1,0><<<BGR+1,1024>>>(srcp, dstp, newip, srcp, dstp,
                                      cntp, offp, csrs, csrw,
                                      bufC, xah, xal, W3, wth, wtl);
        k_gemm_tc<<<NT/128,256>>>(xah, xal, wth, wtl, b3, Ws3, bufB, s0p);
        k_txr<128,1><<<BGR,128>>>(cntp, offp, csrs, csrw, s0p, bs3, newip,
                                  bufB, bufC, out);
    }
}